// round 5
// baseline (speedup 1.0000x reference)
#include <cuda_runtime.h>

typedef unsigned long long ull;

#define NV      100000
#define NE      1600000
#define GRIDW   128
#define G3      (GRIDW*GRIDW*GRIDW)
#define BCAP    128          // neighbor bucket capacity per vertex

// ---------------- device scratch ----------------
__device__ int   g_cursor[NV];
__device__ int   g_csr[NV * BCAP];

__device__ float g_X0[NV * 32];
__device__ float g_X1[NV * 32];
__device__ float g_X2[NV * 64];
__device__ float g_X3[NV * 64];
__device__ float4 g_P[NV];    // h3 @ Wn3
__device__ float4 g_S[NV];    // h3 @ Ws3 + b3

// ---------------- f32x2 helpers ----------------
__device__ __forceinline__ ull pack2(float lo, float hi) {
    ull r; asm("mov.b64 %0, {%1,%2};" : "=l"(r) : "f"(lo), "f"(hi)); return r;
}
__device__ __forceinline__ float2 unpack2(ull v) {
    float2 f; asm("mov.b64 {%0,%1}, %2;" : "=f"(f.x), "=f"(f.y) : "l"(v)); return f;
}
__device__ __forceinline__ ull fma2(ull a, ull b, ull c) {
    ull d; asm("fma.rn.f32x2 %0, %1, %2, %3;" : "=l"(d) : "l"(a), "l"(b), "l"(c)); return d;
}

// ---------------- bucket scatter ----------------
__global__ void k_scatter(const int4* __restrict__ src4, const int4* __restrict__ dst4) {
    int e = blockIdx.x * blockDim.x + threadIdx.x;
    if (e < NE / 4) {
        int4 s = src4[e];
        int4 d = dst4[e];
        int p;
        p = atomicAdd(&g_cursor[d.x], 1); g_csr[d.x * BCAP + p] = s.x;
        p = atomicAdd(&g_cursor[d.y], 1); g_csr[d.y * BCAP + p] = s.y;
        p = atomicAdd(&g_cursor[d.z], 1); g_csr[d.z * BCAP + p] = s.z;
        p = atomicAdd(&g_cursor[d.w], 1); g_csr[d.w * BCAP + p] = s.w;
    }
}

// ---------------- trilinear sampling (+ cursor zeroing fused) ----------------
__global__ void k_sample(const float* __restrict__ img, const float* __restrict__ verts) {
    int tid = blockIdx.x * blockDim.x + threadIdx.x;
    if (tid >= NV * 16) return;
    int v = tid >> 4;
    int c = tid & 15;

    if (c == 0) g_cursor[v] = 0;

    float px = verts[v * 3 + 0];
    float py = verts[v * 3 + 1];
    float pz = verts[v * 3 + 2];

    if (c < 3) {
        float coord = (c == 0) ? px : (c == 1 ? py : pz);
        g_X0[v * 32 + c] = coord * (1.0f / (float)GRIDW);
    }
    if (c < 13) g_X0[v * 32 + 19 + c] = 0.0f;

    float cx = fminf(fmaxf(px, 0.0f), 127.0f);
    float cy = fminf(fmaxf(py, 0.0f), 127.0f);
    float cz = fminf(fmaxf(pz, 0.0f), 127.0f);
    float fx0 = floorf(cx), fy0 = floorf(cy), fz0 = floorf(cz);
    int x0 = (int)fx0, y0 = (int)fy0, z0 = (int)fz0;
    int x1 = min(x0 + 1, 127), y1 = min(y0 + 1, 127), z1 = min(z0 + 1, 127);
    float wx = cx - fx0, wy = cy - fy0, wz = cz - fz0;

    const float* ch = img + (size_t)c * G3;
    int b00 = (x0 << 14) + (y0 << 7);
    int b01 = (x0 << 14) + (y1 << 7);
    int b10 = (x1 << 14) + (y0 << 7);
    int b11 = (x1 << 14) + (y1 << 7);

    float v000 = ch[b00 + z0], v001 = ch[b00 + z1];
    float v010 = ch[b01 + z0], v011 = ch[b01 + z1];
    float v100 = ch[b10 + z0], v101 = ch[b10 + z1];
    float v110 = ch[b11 + z0], v111 = ch[b11 + z1];

    float c00 = v000 * (1.0f - wz) + v001 * wz;
    float c01 = v010 * (1.0f - wz) + v011 * wz;
    float c10 = v100 * (1.0f - wz) + v101 * wz;
    float c11 = v110 * (1.0f - wz) + v111 * wz;

    float val = (c00 * (1.0f - wy) + c01 * wy) * (1.0f - wx)
              + (c10 * (1.0f - wy) + c11 * wy) * wx;

    g_X0[v * 32 + 3 + c] = val;
}

// ---------------- fused edge_conv layer ----------------
// 8 warps/block, 4 vertices per warp (grid covers NV exactly).
// Aggregation: coalesced index prefetch + shfl distribution; PAR neighbors
// per step per vertex (PAR=2 for DINP=64 half-warp, PAR=4 for DINP=32
// quarter-warp); 4 vertices interleaved => 4 LDG.128/lane/step in flight.
template<int DINP, int DOUT, bool RELU>
__global__ void __launch_bounds__(256, 3)
k_layer(const float* __restrict__ X, float* __restrict__ Y,
        const float* __restrict__ Wsg, const float* __restrict__ Wng,
        const float* __restrict__ Bg, int din_real)
{
    constexpr int RSF = DINP + 4;
    constexpr int NQ  = DOUT / 32;
    constexpr int PAR = (DINP == 64) ? 2 : 4;   // neighbors per step
    constexpr int GSZ = 32 / PAR;               // lanes per neighbor

    __shared__ __align__(16) float Ws[DOUT * RSF];
    __shared__ __align__(16) float Wn[DOUT * RSF];
    __shared__ __align__(16) float stg[8][8][DINP];  // [warp][0-3 self, 4-7 nb]
    __shared__ float Bs[DOUT];

    int t = threadIdx.x;
    for (int idx = t; idx < DOUT * DINP; idx += 256) {
        int j = idx / DINP, i = idx % DINP;
        float vs = 0.0f, vn = 0.0f;
        if (i < din_real) { vs = Wsg[i * DOUT + j]; vn = Wng[i * DOUT + j]; }
        Ws[j * RSF + i] = vs;
        Wn[j * RSF + i] = vn;
    }
    if (t < DOUT) Bs[t] = Bg[t];
    __syncthreads();

    int warp = t >> 5;
    int lane = t & 31;
    int sub  = lane / GSZ;            // which neighbor of a PAR-group
    int col  = (lane & (GSZ - 1)) * 4;

    int vbase = (blockIdx.x * 8 + warp) * 4;
    if (vbase >= NV) return;

    int off[4], deg[4];
#pragma unroll
    for (int m = 0; m < 4; m++) {
        int v = vbase + m;
        off[m] = v * BCAP;
        deg[m] = g_cursor[v];
    }
    int dmax = max(max(deg[0], deg[1]), max(deg[2], deg[3]));

    // ---- self rows ----
#pragma unroll
    for (int m = 0; m < 4; m++) {
        if (DINP == 64) {
            float2 xa = *(const float2*)&X[(size_t)(vbase + m) * 64 + 2 * lane];
            *(float2*)&stg[warp][m][2 * lane] = xa;
        } else {
            stg[warp][m][lane] = X[(size_t)(vbase + m) * 32 + lane];
        }
    }

    // ---- neighbor aggregation ----
    float4 agg[4];
#pragma unroll
    for (int m = 0; m < 4; m++) agg[m] = make_float4(0, 0, 0, 0);

    for (int kb = 0; kb < dmax; kb += 32) {
        int idx[4];
#pragma unroll
        for (int m = 0; m < 4; m++)
            idx[m] = (kb + lane < deg[m]) ? g_csr[off[m] + kb + lane] : 0;

        int klim = min(dmax - kb, 32);
#pragma unroll 4
        for (int k = 0; k < klim; k += PAR) {
            int ii = kb + k + sub;
#pragma unroll
            for (int m = 0; m < 4; m++) {
                int s = __shfl_sync(0xFFFFFFFFu, idx[m], k + sub);
                float4 f = make_float4(0, 0, 0, 0);
                if (ii < deg[m]) f = *(const float4*)&X[(size_t)s * DINP + col];
                agg[m].x += f.x; agg[m].y += f.y; agg[m].z += f.z; agg[m].w += f.w;
            }
        }
    }

#pragma unroll
    for (int m = 0; m < 4; m++) {
        if (PAR == 4) {
            agg[m].x += __shfl_xor_sync(0xFFFFFFFFu, agg[m].x, 8);
            agg[m].y += __shfl_xor_sync(0xFFFFFFFFu, agg[m].y, 8);
            agg[m].z += __shfl_xor_sync(0xFFFFFFFFu, agg[m].z, 8);
            agg[m].w += __shfl_xor_sync(0xFFFFFFFFu, agg[m].w, 8);
        }
        agg[m].x += __shfl_xor_sync(0xFFFFFFFFu, agg[m].x, 16);
        agg[m].y += __shfl_xor_sync(0xFFFFFFFFu, agg[m].y, 16);
        agg[m].z += __shfl_xor_sync(0xFFFFFFFFu, agg[m].z, 16);
        agg[m].w += __shfl_xor_sync(0xFFFFFFFFu, agg[m].w, 16);
        float inv = 1.0f / fmaxf((float)deg[m], 1.0f);
        agg[m].x *= inv; agg[m].y *= inv; agg[m].z *= inv; agg[m].w *= inv;
        if (sub == 0) *(float4*)&stg[warp][4 + m][col] = agg[m];
    }
    __syncwarp();

    // ---- register-tiled dual GEMM (4 vertices x NQ outputs/lane) ----
    ull acc[NQ][4];
#pragma unroll
    for (int q = 0; q < NQ; q++) {
        ull b = pack2(Bs[q * 32 + lane], 0.0f);
#pragma unroll
        for (int m = 0; m < 4; m++) acc[q][m] = b;
    }

#pragma unroll 2
    for (int i0 = 0; i0 < DINP; i0 += 4) {
        ulonglong2 ws[NQ], wn[NQ];
#pragma unroll
        for (int q = 0; q < NQ; q++) {
            ws[q] = *(const ulonglong2*)&Ws[(q * 32 + lane) * RSF + i0];
            wn[q] = *(const ulonglong2*)&Wn[(q * 32 + lane) * RSF + i0];
        }
#pragma unroll
        for (int m = 0; m < 4; m++) {
            ulonglong2 xs2 = *(const ulonglong2*)&stg[warp][m][i0];
            ulonglong2 ns2 = *(const ulonglong2*)&stg[warp][4 + m][i0];
#pragma unroll
            for (int q = 0; q < NQ; q++) {
                acc[q][m] = fma2(xs2.x, ws[q].x, acc[q][m]);
                acc[q][m] = fma2(xs2.y, ws[q].y, acc[q][m]);
                acc[q][m] = fma2(ns2.x, wn[q].x, acc[q][m]);
                acc[q][m] = fma2(ns2.y, wn[q].y, acc[q][m]);
            }
        }
    }

    // ---- store ----
#pragma unroll
    for (int m = 0; m < 4; m++) {
        int v = vbase + m;
#pragma unroll
        for (int q = 0; q < NQ; q++) {
            float2 u = unpack2(acc[q][m]);
            float y = u.x + u.y;
            if (RELU) y = fmaxf(y, 0.3f * y);
            Y[(size_t)v * DOUT + q * 32 + lane] = y;
        }
    }
}

// ---------------- final layer, stage 1: project h3 by Ws3/Wn3 ----------------
__global__ void __launch_bounds__(256)
k_proj(const float* __restrict__ X,
       const float* __restrict__ Wsg, const float* __restrict__ Wng,
       const float* __restrict__ Bg)
{
    int t = threadIdx.x;
    int warp = t >> 5, lane = t & 31;

    float ws[2][3], wn[2][3];
#pragma unroll
    for (int e = 0; e < 2; e++)
#pragma unroll
        for (int c = 0; c < 3; c++) {
            ws[e][c] = Wsg[(2 * lane + e) * 3 + c];
            wn[e][c] = Wng[(2 * lane + e) * 3 + c];
        }

    int v = blockIdx.x * 8 + warp;
    if (v >= NV) return;

    float2 xv = *(const float2*)&X[(size_t)v * 64 + 2 * lane];

    float as[3], an[3];
#pragma unroll
    for (int c = 0; c < 3; c++) {
        as[c] = xv.x * ws[0][c] + xv.y * ws[1][c];
        an[c] = xv.x * wn[0][c] + xv.y * wn[1][c];
    }
#pragma unroll
    for (int off = 16; off > 0; off >>= 1) {
#pragma unroll
        for (int c = 0; c < 3; c++) {
            as[c] += __shfl_xor_sync(0xFFFFFFFFu, as[c], off);
            an[c] += __shfl_xor_sync(0xFFFFFFFFu, an[c], off);
        }
    }
    if (lane == 0) {
        g_S[v] = make_float4(as[0] + Bg[0], as[1] + Bg[1], as[2] + Bg[2], 0.0f);
        g_P[v] = make_float4(an[0], an[1], an[2], 0.0f);
    }
}

// ---------------- final layer, stage 2: 3-wide gather + output ----------------
__global__ void __launch_bounds__(256)
k_fin2(float* __restrict__ out, const float* __restrict__ verts)
{
    int v = blockIdx.x * blockDim.x + threadIdx.x;
    if (v >= NV) return;

    int d = g_cursor[v];
    int o = v * BCAP;
    float ax = 0.0f, ay = 0.0f, az = 0.0f;
    int k = 0;
    for (; k + 4 <= d; k += 4) {
        int s0 = g_csr[o + k],     s1 = g_csr[o + k + 1];
        int s2 = g_csr[o + k + 2], s3 = g_csr[o + k + 3];
        float4 p0 = g_P[s0], p1 = g_P[s1], p2 = g_P[s2], p3 = g_P[s3];
        ax += (p0.x + p1.x) + (p2.x + p3.x);
        ay += (p0.y + p1.y) + (p2.y + p3.y);
        az += (p0.z + p1.z) + (p2.z + p3.z);
    }
    for (; k < d; k++) {
        float4 p = g_P[g_csr[o + k]];
        ax += p.x; ay += p.y; az += p.z;
    }
    float idg = 1.0f / fmaxf((float)d, 1.0f);
    float4 S = g_S[v];
    out[v * 3 + 0] = verts[v * 3 + 0] + 0.1f * (S.x + idg * ax);
    out[v * 3 + 1] = verts[v * 3 + 1] + 0.1f * (S.y + idg * ay);
    out[v * 3 + 2] = verts[v * 3 + 2] + 0.1f * (S.z + idg * az);
}

// ---------------- launch ----------------
extern "C" void kernel_launch(void* const* d_in, const int* in_sizes, int n_in,
                              void* d_out, int out_size)
{
    const float* img   = (const float*)d_in[0];
    const float* verts = (const float*)d_in[1];
    const int*   esrc  = (const int*)d_in[2];
    const int*   edst  = (const int*)d_in[3];
    const float* ws0 = (const float*)d_in[4];
    const float* wn0 = (const float*)d_in[5];
    const float* b0  = (const float*)d_in[6];
    const float* ws1 = (const float*)d_in[7];
    const float* wn1 = (const float*)d_in[8];
    const float* b1  = (const float*)d_in[9];
    const float* ws2 = (const float*)d_in[10];
    const float* wn2 = (const float*)d_in[11];
    const float* b2  = (const float*)d_in[12];
    const float* ws3 = (const float*)d_in[13];
    const float* wn3 = (const float*)d_in[14];
    const float* b3  = (const float*)d_in[15];
    float* out = (float*)d_out;

    float *x0p, *x1p, *x2p, *x3p;
    cudaGetSymbolAddress((void**)&x0p, g_X0);
    cudaGetSymbolAddress((void**)&x1p, g_X1);
    cudaGetSymbolAddress((void**)&x2p, g_X2);
    cudaGetSymbolAddress((void**)&x3p, g_X3);

    const int TB = 256;
    const int GL = (NV + 31) / 32;   // 3125: 8 warps x 4 verts per block

    k_sample<<<(NV * 16 + TB - 1) / TB, TB>>>(img, verts);
    k_scatter<<<(NE / 4 + TB - 1) / TB, TB>>>((const int4*)esrc, (const int4*)edst);

    k_layer<32, 32, true><<<GL, TB>>>(x0p, x1p, ws0, wn0, b0, 19);
    k_layer<32, 64, true><<<GL, TB>>>(x1p, x2p, ws1, wn1, b1, 32);
    k_layer<64, 64, true><<<GL, TB>>>(x2p, x3p, ws2, wn2, b2, 64);
    k_proj<<<(NV + 7) / 8, TB>>>(x3p, ws3, wn3, b3);
    k_fin2<<<(NV + TB - 1) / TB, TB>>>(out, verts);
}

// round 6
// speedup vs baseline: 1.0010x; 1.0010x over previous
#include <cuda_runtime.h>
#include <cuda_bf16.h>

typedef unsigned long long ull;
typedef unsigned int u32;

#define NV      100000
#define NE      1600000
#define GRIDW   128
#define G3      (GRIDW*GRIDW*GRIDW)
#define BCAP    128          // neighbor bucket capacity per vertex

// ---------------- device scratch ----------------
__device__ int   g_cursor[NV];
__device__ int   g_csr[NV * BCAP];

__device__ __align__(16) __nv_bfloat16 g_X0[NV * 32];
__device__ __align__(16) __nv_bfloat16 g_X1[NV * 32];
__device__ __align__(16) __nv_bfloat16 g_X2[NV * 64];
__device__ __align__(16) __nv_bfloat16 g_X3[NV * 64];
__device__ float4 g_P[NV];    // h3 @ Wn3
__device__ float4 g_S[NV];    // h3 @ Ws3 + b3

// ---------------- f32x2 helpers ----------------
__device__ __forceinline__ ull pack2(float lo, float hi) {
    ull r; asm("mov.b64 %0, {%1,%2};" : "=l"(r) : "f"(lo), "f"(hi)); return r;
}
__device__ __forceinline__ float2 unpack2(ull v) {
    float2 f; asm("mov.b64 {%0,%1}, %2;" : "=f"(f.x), "=f"(f.y) : "l"(v)); return f;
}
__device__ __forceinline__ ull fma2(ull a, ull b, ull c) {
    ull d; asm("fma.rn.f32x2 %0, %1, %2, %3;" : "=l"(d) : "l"(a), "l"(b), "l"(c)); return d;
}
__device__ __forceinline__ ull add2(ull a, ull b) {
    ull d; asm("add.rn.f32x2 %0, %1, %2;" : "=l"(d) : "l"(a), "l"(b)); return d;
}
__device__ __forceinline__ ull mul2(ull a, ull b) {
    ull d; asm("mul.rn.f32x2 %0, %1, %2;" : "=l"(d) : "l"(a), "l"(b)); return d;
}
// bf16x2 (packed in u32, elem i low half) -> f32x2 (lo = elem i)
__device__ __forceinline__ ull bf2f2(u32 p) {
    u32 lo = p << 16;
    u32 hi = p & 0xFFFF0000u;
    ull r; asm("mov.b64 %0, {%1,%2};" : "=l"(r) : "r"(lo), "r"(hi)); return r;
}
// f32x2 -> bf16x2 (u32), round-to-nearest
__device__ __forceinline__ u32 f2bf2(ull v) {
    float2 f = unpack2(v);
    __nv_bfloat162 b = __float22bfloat162_rn(f);
    return *(u32*)&b;
}

// ---------------- bucket scatter ----------------
__global__ void k_scatter(const int4* __restrict__ src4, const int4* __restrict__ dst4) {
    int e = blockIdx.x * blockDim.x + threadIdx.x;
    if (e < NE / 4) {
        int4 s = src4[e];
        int4 d = dst4[e];
        int p;
        p = atomicAdd(&g_cursor[d.x], 1); g_csr[d.x * BCAP + p] = s.x;
        p = atomicAdd(&g_cursor[d.y], 1); g_csr[d.y * BCAP + p] = s.y;
        p = atomicAdd(&g_cursor[d.z], 1); g_csr[d.z * BCAP + p] = s.z;
        p = atomicAdd(&g_cursor[d.w], 1); g_csr[d.w * BCAP + p] = s.w;
    }
}

// ---------------- trilinear sampling (+ cursor zeroing fused) ----------------
__global__ void k_sample(const float* __restrict__ img, const float* __restrict__ verts) {
    int tid = blockIdx.x * blockDim.x + threadIdx.x;
    if (tid >= NV * 16) return;
    int v = tid >> 4;
    int c = tid & 15;

    if (c == 0) g_cursor[v] = 0;

    float px = verts[v * 3 + 0];
    float py = verts[v * 3 + 1];
    float pz = verts[v * 3 + 2];

    if (c < 3) {
        float coord = (c == 0) ? px : (c == 1 ? py : pz);
        g_X0[v * 32 + c] = __float2bfloat16(coord * (1.0f / (float)GRIDW));
    }
    if (c < 13) g_X0[v * 32 + 19 + c] = __float2bfloat16(0.0f);

    float cx = fminf(fmaxf(px, 0.0f), 127.0f);
    float cy = fminf(fmaxf(py, 0.0f), 127.0f);
    float cz = fminf(fmaxf(pz, 0.0f), 127.0f);
    float fx0 = floorf(cx), fy0 = floorf(cy), fz0 = floorf(cz);
    int x0 = (int)fx0, y0 = (int)fy0, z0 = (int)fz0;
    int x1 = min(x0 + 1, 127), y1 = min(y0 + 1, 127), z1 = min(z0 + 1, 127);
    float wx = cx - fx0, wy = cy - fy0, wz = cz - fz0;

    const float* ch = img + (size_t)c * G3;
    int b00 = (x0 << 14) + (y0 << 7);
    int b01 = (x0 << 14) + (y1 << 7);
    int b10 = (x1 << 14) + (y0 << 7);
    int b11 = (x1 << 14) + (y1 << 7);

    float v000 = ch[b00 + z0], v001 = ch[b00 + z1];
    float v010 = ch[b01 + z0], v011 = ch[b01 + z1];
    float v100 = ch[b10 + z0], v101 = ch[b10 + z1];
    float v110 = ch[b11 + z0], v111 = ch[b11 + z1];

    float c00 = v000 * (1.0f - wz) + v001 * wz;
    float c01 = v010 * (1.0f - wz) + v011 * wz;
    float c10 = v100 * (1.0f - wz) + v101 * wz;
    float c11 = v110 * (1.0f - wz) + v111 * wz;

    float val = (c00 * (1.0f - wy) + c01 * wy) * (1.0f - wx)
              + (c10 * (1.0f - wy) + c11 * wy) * wx;

    g_X0[v * 32 + 3 + c] = __float2bfloat16(val);
}

// ---------------- fused edge_conv layer (bf16 activations) ----------------
// 8 warps/block, 4 vertices per warp. Gather rows are bf16:
//   DINP=32: 64B rows, 4 lanes/row, 8 neighbors per warp-instr
//   DINP=64: 128B rows, 8 lanes/row, 4 neighbors per warp-instr
// GEMM: bf16 x staged in smem (LDS.128 = 8 k-values), f32 weights, f32x2 FMAs.
template<int DINP, int DOUT, bool RELU>
__global__ void __launch_bounds__(256, 3)
k_layer(const __nv_bfloat16* __restrict__ X, __nv_bfloat16* __restrict__ Y,
        const float* __restrict__ Wsg, const float* __restrict__ Wng,
        const float* __restrict__ Bg, int din_real)
{
    constexpr int RSF = DINP + 4;
    constexpr int NQ  = DOUT / 32;
    constexpr int GSZ = (DINP == 64) ? 8 : 4;   // lanes per row
    constexpr int PAR = 32 / GSZ;               // rows in flight per instr
    constexpr int NU  = 2;                      // ull accumulators per lane... (8 f32 per 16B seg -> 4)

    __shared__ __align__(16) float Ws[DOUT * RSF];
    __shared__ __align__(16) float Wn[DOUT * RSF];
    __shared__ __align__(16) __nv_bfloat16 stgb[8][8][DINP];  // [warp][0-3 self, 4-7 nb]
    __shared__ float Bs[DOUT];

    int t = threadIdx.x;
    for (int idx = t; idx < DOUT * DINP; idx += 256) {
        int j = idx / DINP, i = idx % DINP;
        float vs = 0.0f, vn = 0.0f;
        if (i < din_real) { vs = Wsg[i * DOUT + j]; vn = Wng[i * DOUT + j]; }
        Ws[j * RSF + i] = vs;
        Wn[j * RSF + i] = vn;
    }
    if (t < DOUT) Bs[t] = Bg[t];
    __syncthreads();

    int warp = t >> 5;
    int lane = t & 31;
    int sub  = lane / GSZ;               // neighbor slot within PAR group
    int cole = (lane & (GSZ - 1)) * 8;   // element offset of this lane's 16B segment

    int vbase = (blockIdx.x * 8 + warp) * 4;
    if (vbase >= NV) return;

    int off[4], deg[4];
#pragma unroll
    for (int m = 0; m < 4; m++) {
        int v = vbase + m;
        off[m] = v * BCAP;
        deg[m] = g_cursor[v];
    }
    int dmax = max(max(deg[0], deg[1]), max(deg[2], deg[3]));

    // ---- self rows (bf16 copy) ----
#pragma unroll
    for (int m = 0; m < 4; m++) {
        if (DINP == 64) {
            *(u32*)&stgb[warp][m][2 * lane] = *(const u32*)&X[(size_t)(vbase + m) * 64 + 2 * lane];
        } else {
            if (lane < 16)
                *(u32*)&stgb[warp][m][2 * lane] = *(const u32*)&X[(size_t)(vbase + m) * 32 + 2 * lane];
        }
    }

    // ---- neighbor aggregation (f32x2 accumulators, 4 per vertex = 8 f32) ----
    ull agg[4][4];
#pragma unroll
    for (int m = 0; m < 4; m++)
#pragma unroll
        for (int j = 0; j < 4; j++) agg[m][j] = 0ull;

    for (int kb = 0; kb < dmax; kb += 32) {
        int idx[4];
#pragma unroll
        for (int m = 0; m < 4; m++)
            idx[m] = (kb + lane < deg[m]) ? g_csr[off[m] + kb + lane] : 0;

        int klim = min(dmax - kb, 32);
#pragma unroll 2
        for (int k = 0; k < klim; k += PAR) {
            int ii = kb + k + sub;
#pragma unroll
            for (int m = 0; m < 4; m++) {
                int s = __shfl_sync(0xFFFFFFFFu, idx[m], k + sub);
                uint4 f = make_uint4(0, 0, 0, 0);
                if (ii < deg[m])
                    f = *(const uint4*)&X[(size_t)s * DINP + cole];
                agg[m][0] = add2(agg[m][0], bf2f2(f.x));
                agg[m][1] = add2(agg[m][1], bf2f2(f.y));
                agg[m][2] = add2(agg[m][2], bf2f2(f.z));
                agg[m][3] = add2(agg[m][3], bf2f2(f.w));
            }
        }
    }

#pragma unroll
    for (int m = 0; m < 4; m++) {
        // reduce across sub groups (lane xor GSZ, 2*GSZ, 16)
#pragma unroll
        for (int msk = GSZ; msk < 32; msk <<= 1) {
#pragma unroll
            for (int j = 0; j < 4; j++)
                agg[m][j] = add2(agg[m][j], __shfl_xor_sync(0xFFFFFFFFu, agg[m][j], msk));
        }
        float inv = 1.0f / fmaxf((float)deg[m], 1.0f);
        ull inv2 = pack2(inv, inv);
        if (sub == 0) {
            uint4 o;
            o.x = f2bf2(mul2(agg[m][0], inv2));
            o.y = f2bf2(mul2(agg[m][1], inv2));
            o.z = f2bf2(mul2(agg[m][2], inv2));
            o.w = f2bf2(mul2(agg[m][3], inv2));
            *(uint4*)&stgb[warp][4 + m][cole] = o;
        }
    }
    __syncwarp();

    // ---- register-tiled dual GEMM (4 vertices x NQ outputs/lane) ----
    ull acc[NQ][4];
#pragma unroll
    for (int q = 0; q < NQ; q++) {
        ull b = pack2(Bs[q * 32 + lane], 0.0f);
#pragma unroll
        for (int m = 0; m < 4; m++) acc[q][m] = b;
    }

#pragma unroll
    for (int i0 = 0; i0 < DINP; i0 += 8) {
        ulonglong2 wsA[NQ], wsB[NQ], wnA[NQ], wnB[NQ];
#pragma unroll
        for (int q = 0; q < NQ; q++) {
            wsA[q] = *(const ulonglong2*)&Ws[(q * 32 + lane) * RSF + i0];
            wsB[q] = *(const ulonglong2*)&Ws[(q * 32 + lane) * RSF + i0 + 4];
            wnA[q] = *(const ulonglong2*)&Wn[(q * 32 + lane) * RSF + i0];
            wnB[q] = *(const ulonglong2*)&Wn[(q * 32 + lane) * RSF + i0 + 4];
        }
#pragma unroll
        for (int m = 0; m < 4; m++) {
            uint4 xu = *(const uint4*)&stgb[warp][m][i0];
            uint4 nu = *(const uint4*)&stgb[warp][4 + m][i0];
            ull x01 = bf2f2(xu.x), x23 = bf2f2(xu.y), x45 = bf2f2(xu.z), x67 = bf2f2(xu.w);
            ull n01 = bf2f2(nu.x), n23 = bf2f2(nu.y), n45 = bf2f2(nu.z), n67 = bf2f2(nu.w);
#pragma unroll
            for (int q = 0; q < NQ; q++) {
                acc[q][m] = fma2(x01, wsA[q].x, acc[q][m]);
                acc[q][m] = fma2(x23, wsA[q].y, acc[q][m]);
                acc[q][m] = fma2(x45, wsB[q].x, acc[q][m]);
                acc[q][m] = fma2(x67, wsB[q].y, acc[q][m]);
                acc[q][m] = fma2(n01, wnA[q].x, acc[q][m]);
                acc[q][m] = fma2(n23, wnA[q].y, acc[q][m]);
                acc[q][m] = fma2(n45, wnB[q].x, acc[q][m]);
                acc[q][m] = fma2(n67, wnB[q].y, acc[q][m]);
            }
        }
    }

    // ---- store (bf16) ----
#pragma unroll
    for (int m = 0; m < 4; m++) {
        int v = vbase + m;
#pragma unroll
        for (int q = 0; q < NQ; q++) {
            float2 u = unpack2(acc[q][m]);
            float y = u.x + u.y;
            if (RELU) y = fmaxf(y, 0.3f * y);
            Y[(size_t)v * DOUT + q * 32 + lane] = __float2bfloat16(y);
        }
    }
}

// ---------------- final layer, stage 1: project h3 by Ws3/Wn3 ----------------
__global__ void __launch_bounds__(256)
k_proj(const __nv_bfloat16* __restrict__ X,
       const float* __restrict__ Wsg, const float* __restrict__ Wng,
       const float* __restrict__ Bg)
{
    int t = threadIdx.x;
    int warp = t >> 5, lane = t & 31;

    float ws[2][3], wn[2][3];
#pragma unroll
    for (int e = 0; e < 2; e++)
#pragma unroll
        for (int c = 0; c < 3; c++) {
            ws[e][c] = Wsg[(2 * lane + e) * 3 + c];
            wn[e][c] = Wng[(2 * lane + e) * 3 + c];
        }

    int v = blockIdx.x * 8 + warp;
    if (v >= NV) return;

    u32 xp = *(const u32*)&X[(size_t)v * 64 + 2 * lane];
    float2 xv = unpack2(bf2f2(xp));

    float as[3], an[3];
#pragma unroll
    for (int c = 0; c < 3; c++) {
        as[c] = xv.x * ws[0][c] + xv.y * ws[1][c];
        an[c] = xv.x * wn[0][c] + xv.y * wn[1][c];
    }
#pragma unroll
    for (int off = 16; off > 0; off >>= 1) {
#pragma unroll
        for (int c = 0; c < 3; c++) {
            as[c] += __shfl_xor_sync(0xFFFFFFFFu, as[c], off);
            an[c] += __shfl_xor_sync(0xFFFFFFFFu, an[c], off);
        }
    }
    if (lane == 0) {
        g_S[v] = make_float4(as[0] + Bg[0], as[1] + Bg[1], as[2] + Bg[2], 0.0f);
        g_P[v] = make_float4(an[0], an[1], an[2], 0.0f);
    }
}

// ---------------- final layer, stage 2: 3-wide gather + output ----------------
__global__ void __launch_bounds__(256)
k_fin2(float* __restrict__ out, const float* __restrict__ verts)
{
    int v = blockIdx.x * blockDim.x + threadIdx.x;
    if (v >= NV) return;

    int d = g_cursor[v];
    int o = v * BCAP;
    float ax = 0.0f, ay = 0.0f, az = 0.0f;
    int k = 0;
    for (; k + 4 <= d; k += 4) {
        int s0 = g_csr[o + k],     s1 = g_csr[o + k + 1];
        int s2 = g_csr[o + k + 2], s3 = g_csr[o + k + 3];
        float4 p0 = g_P[s0], p1 = g_P[s1], p2 = g_P[s2], p3 = g_P[s3];
        ax += (p0.x + p1.x) + (p2.x + p3.x);
        ay += (p0.y + p1.y) + (p2.y + p3.y);
        az += (p0.z + p1.z) + (p2.z + p3.z);
    }
    for (; k < d; k++) {
        float4 p = g_P[g_csr[o + k]];
        ax += p.x; ay += p.y; az += p.z;
    }
    float idg = 1.0f / fmaxf((float)d, 1.0f);
    float4 S = g_S[v];
    out[v * 3 + 0] = verts[v * 3 + 0] + 0.1f * (S.x + idg * ax);
    out[v * 3 + 1] = verts[v * 3 + 1] + 0.1f * (S.y + idg * ay);
    out[v * 3 + 2] = verts[v * 3 + 2] + 0.1f * (S.z + idg * az);
}

// ---------------- launch ----------------
extern "C" void kernel_launch(void* const* d_in, const int* in_sizes, int n_in,
                              void* d_out, int out_size)
{
    const float* img   = (const float*)d_in[0];
    const float* verts = (const float*)d_in[1];
    const int*   esrc  = (const int*)d_in[2];
    const int*   edst  = (const int*)d_in[3];
    const float* ws0 = (const float*)d_in[4];
    const float* wn0 = (const float*)d_in[5];
    const float* b0  = (const float*)d_in[6];
    const float* ws1 = (const float*)d_in[7];
    const float* wn1 = (const float*)d_in[8];
    const float* b1  = (const float*)d_in[9];
    const float* ws2 = (const float*)d_in[10];
    const float* wn2 = (const float*)d_in[11];
    const float* b2  = (const float*)d_in[12];
    const float* ws3 = (const float*)d_in[13];
    const float* wn3 = (const float*)d_in[14];
    const float* b3  = (const float*)d_in[15];
    float* out = (float*)d_out;

    __nv_bfloat16 *x0p, *x1p, *x2p, *x3p;
    cudaGetSymbolAddress((void**)&x0p, g_X0);
    cudaGetSymbolAddress((void**)&x1p, g_X1);
    cudaGetSymbolAddress((void**)&x2p, g_X2);
    cudaGetSymbolAddress((void**)&x3p, g_X3);

    const int TB = 256;
    const int GL = (NV + 31) / 32;   // 3125: 8 warps x 4 verts per block

    k_sample<<<(NV * 16 + TB - 1) / TB, TB>>>(img, verts);
    k_scatter<<<(NE / 4 + TB - 1) / TB, TB>>>((const int4*)esrc, (const int4*)edst);

    k_layer<32, 32, true><<<GL, TB>>>(x0p, x1p, ws0, wn0, b0, 19);
    k_layer<32, 64, true><<<GL, TB>>>(x1p, x2p, ws1, wn1, b1, 32);
    k_layer<64, 64, true><<<GL, TB>>>(x2p, x3p, ws2, wn2, b2, 64);
    k_proj<<<(NV + 7) / 8, TB>>>(x3p, ws3, wn3, b3);
    k_fin2<<<(NV + TB - 1) / TB, TB>>>(out, verts);
}

// round 7
// speedup vs baseline: 1.3648x; 1.3635x over previous
#include <cuda_runtime.h>
#include <cuda_bf16.h>

typedef unsigned long long ull;
typedef unsigned int u32;

#define NV      100000
#define NE      1600000
#define GRIDW   128
#define G3      (GRIDW*GRIDW*GRIDW)
#define BCAP    128          // neighbor bucket capacity per vertex

// ---------------- device scratch ----------------
__device__ int   g_cursor[NV];
__device__ int   g_csr[NV * BCAP];

__device__ __align__(16) __nv_bfloat16 g_X0[NV * 32];
__device__ __align__(16) __nv_bfloat16 g_X1[NV * 32];
__device__ __align__(16) __nv_bfloat16 g_X2[NV * 64];
__device__ __align__(16) __nv_bfloat16 g_X3[NV * 64];
__device__ __align__(16) __nv_bfloat16 g_G32[NV * 32];   // aggregated (32-wide layers)
__device__ __align__(16) __nv_bfloat16 g_G64[NV * 64];   // aggregated (64-wide layer)
__device__ float4 g_P[NV];    // h3 @ Wn3
__device__ float4 g_S[NV];    // h3 @ Ws3 + b3

// ---------------- helpers ----------------
__device__ __forceinline__ ull pack2(float lo, float hi) {
    ull r; asm("mov.b64 %0, {%1,%2};" : "=l"(r) : "f"(lo), "f"(hi)); return r;
}
__device__ __forceinline__ float2 unpack2(ull v) {
    float2 f; asm("mov.b64 {%0,%1}, %2;" : "=f"(f.x), "=f"(f.y) : "l"(v)); return f;
}
__device__ __forceinline__ ull add2(ull a, ull b) {
    ull d; asm("add.rn.f32x2 %0, %1, %2;" : "=l"(d) : "l"(a), "l"(b)); return d;
}
__device__ __forceinline__ ull mul2(ull a, ull b) {
    ull d; asm("mul.rn.f32x2 %0, %1, %2;" : "=l"(d) : "l"(a), "l"(b)); return d;
}
__device__ __forceinline__ ull bf2f2(u32 p) {
    u32 lo = p << 16;
    u32 hi = p & 0xFFFF0000u;
    ull r; asm("mov.b64 %0, {%1,%2};" : "=l"(r) : "r"(lo), "r"(hi)); return r;
}
__device__ __forceinline__ u32 f2bf2(ull v) {
    float2 f = unpack2(v);
    __nv_bfloat162 b = __float22bfloat162_rn(f);
    return *(u32*)&b;
}
__device__ __forceinline__ u32 smaddr(const void* p) {
    return (u32)__cvta_generic_to_shared(p);
}
__device__ __forceinline__ void ldsm_x4(u32& r0, u32& r1, u32& r2, u32& r3, u32 a) {
    asm volatile("ldmatrix.sync.aligned.m8n8.x4.shared.b16 {%0,%1,%2,%3}, [%4];"
                 : "=r"(r0), "=r"(r1), "=r"(r2), "=r"(r3) : "r"(a));
}
__device__ __forceinline__ void ldsm_x2(u32& r0, u32& r1, u32 a) {
    asm volatile("ldmatrix.sync.aligned.m8n8.x2.shared.b16 {%0,%1}, [%2];"
                 : "=r"(r0), "=r"(r1) : "r"(a));
}
__device__ __forceinline__ void mma_bf16(float& d0, float& d1, float& d2, float& d3,
                                         u32 a0, u32 a1, u32 a2, u32 a3,
                                         u32 b0, u32 b1) {
    asm volatile(
        "mma.sync.aligned.m16n8k16.row.col.f32.bf16.bf16.f32 "
        "{%0,%1,%2,%3}, {%4,%5,%6,%7}, {%8,%9}, {%0,%1,%2,%3};"
        : "+f"(d0), "+f"(d1), "+f"(d2), "+f"(d3)
        : "r"(a0), "r"(a1), "r"(a2), "r"(a3), "r"(b0), "r"(b1));
}

// ---------------- bucket scatter ----------------
__global__ void k_scatter(const int4* __restrict__ src4, const int4* __restrict__ dst4) {
    int e = blockIdx.x * blockDim.x + threadIdx.x;
    if (e < NE / 4) {
        int4 s = src4[e];
        int4 d = dst4[e];
        int p;
        p = atomicAdd(&g_cursor[d.x], 1); g_csr[d.x * BCAP + p] = s.x;
        p = atomicAdd(&g_cursor[d.y], 1); g_csr[d.y * BCAP + p] = s.y;
        p = atomicAdd(&g_cursor[d.z], 1); g_csr[d.z * BCAP + p] = s.z;
        p = atomicAdd(&g_cursor[d.w], 1); g_csr[d.w * BCAP + p] = s.w;
    }
}

// ---------------- trilinear sampling (+ cursor zeroing fused) ----------------
__global__ void k_sample(const float* __restrict__ img, const float* __restrict__ verts) {
    int tid = blockIdx.x * blockDim.x + threadIdx.x;
    if (tid >= NV * 16) return;
    int v = tid >> 4;
    int c = tid & 15;

    if (c == 0) g_cursor[v] = 0;

    float px = verts[v * 3 + 0];
    float py = verts[v * 3 + 1];
    float pz = verts[v * 3 + 2];

    if (c < 3) {
        float coord = (c == 0) ? px : (c == 1 ? py : pz);
        g_X0[v * 32 + c] = __float2bfloat16(coord * (1.0f / (float)GRIDW));
    }
    if (c < 13) g_X0[v * 32 + 19 + c] = __float2bfloat16(0.0f);

    float cx = fminf(fmaxf(px, 0.0f), 127.0f);
    float cy = fminf(fmaxf(py, 0.0f), 127.0f);
    float cz = fminf(fmaxf(pz, 0.0f), 127.0f);
    float fx0 = floorf(cx), fy0 = floorf(cy), fz0 = floorf(cz);
    int x0 = (int)fx0, y0 = (int)fy0, z0 = (int)fz0;
    int x1 = min(x0 + 1, 127), y1 = min(y0 + 1, 127), z1 = min(z0 + 1, 127);
    float wx = cx - fx0, wy = cy - fy0, wz = cz - fz0;

    const float* ch = img + (size_t)c * G3;
    int b00 = (x0 << 14) + (y0 << 7);
    int b01 = (x0 << 14) + (y1 << 7);
    int b10 = (x1 << 14) + (y0 << 7);
    int b11 = (x1 << 14) + (y1 << 7);

    float v000 = ch[b00 + z0], v001 = ch[b00 + z1];
    float v010 = ch[b01 + z0], v011 = ch[b01 + z1];
    float v100 = ch[b10 + z0], v101 = ch[b10 + z1];
    float v110 = ch[b11 + z0], v111 = ch[b11 + z1];

    float c00 = v000 * (1.0f - wz) + v001 * wz;
    float c01 = v010 * (1.0f - wz) + v011 * wz;
    float c10 = v100 * (1.0f - wz) + v101 * wz;
    float c11 = v110 * (1.0f - wz) + v111 * wz;

    float val = (c00 * (1.0f - wy) + c01 * wy) * (1.0f - wx)
              + (c10 * (1.0f - wy) + c11 * wy) * wx;

    g_X0[v * 32 + 3 + c] = __float2bfloat16(val);
}

// ---------------- gather: mean of neighbor rows (64-wide), warp/vertex ----------------
__global__ void __launch_bounds__(256)
k_gather64(const __nv_bfloat16* __restrict__ X, __nv_bfloat16* __restrict__ G)
{
    int warp = threadIdx.x >> 5, lane = threadIdx.x & 31;
    int v = blockIdx.x * 8 + warp;
    if (v >= NV) return;

    int d = g_cursor[v];
    int o = v * BCAP;
    ull acc = 0ull;
    for (int kb = 0; kb < d; kb += 32) {
        int idx = (kb + lane < d) ? g_csr[o + kb + lane] : 0;
        int klim = min(d - kb, 32);
#pragma unroll 4
        for (int k = 0; k < klim; k++) {
            int s = __shfl_sync(0xFFFFFFFFu, idx, k);
            u32 p = *(const u32*)&X[(size_t)s * 64 + 2 * lane];
            acc = add2(acc, bf2f2(p));
        }
    }
    float inv = 1.0f / fmaxf((float)d, 1.0f);
    acc = mul2(acc, pack2(inv, inv));
    *(u32*)&G[(size_t)v * 64 + 2 * lane] = f2bf2(acc);
}

// ---------------- gather (32-wide): warp handles 2 vertices ----------------
__global__ void __launch_bounds__(256)
k_gather32(const __nv_bfloat16* __restrict__ X, __nv_bfloat16* __restrict__ G)
{
    int warp = threadIdx.x >> 5, lane = threadIdx.x & 31;
    int hl = lane & 15, half = lane >> 4;
    int v0 = (blockIdx.x * 8 + warp) * 2;
    if (v0 >= NV) return;

    int vme = v0 + half;                 // NV even -> always valid
    int dA = g_cursor[v0], dB = g_cursor[v0 + 1];
    int dme = half ? dB : dA;
    int o = vme * BCAP;
    int dmax = max(dA, dB);

    ull acc = 0ull;
    for (int kb = 0; kb < dmax; kb += 16) {
        int idx = (kb + hl < dme) ? g_csr[o + kb + hl] : 0;
        int klim = min(dmax - kb, 16);
#pragma unroll 4
        for (int k = 0; k < klim; k++) {
            int s = __shfl_sync(0xFFFFFFFFu, idx, (half << 4) + k);
            if (kb + k < dme) {
                u32 p = *(const u32*)&X[(size_t)s * 32 + 2 * hl];
                acc = add2(acc, bf2f2(p));
            }
        }
    }
    float inv = 1.0f / fmaxf((float)dme, 1.0f);
    acc = mul2(acc, pack2(inv, inv));
    *(u32*)&G[(size_t)vme * 32 + 2 * hl] = f2bf2(acc);
}

// ---------------- tensor-core layer GEMM ----------------
// Y[64 x DOUT] = leaky([X|G][64 x K] @ Wt^T + b), K = 2*DINP, bf16 HMMA, f32 acc.
// Block: 256 threads = 8 warps (4 m-tiles x 2 n-halves), 64 vertices per block.
template<int K, int DOUT, bool RELU>
__global__ void __launch_bounds__(256)
k_gemm(const __nv_bfloat16* __restrict__ X, const __nv_bfloat16* __restrict__ G,
       __nv_bfloat16* __restrict__ Y,
       const float* __restrict__ Wsg, const float* __restrict__ Wng,
       const float* __restrict__ Bg, int din_real)
{
    constexpr int RS  = K + 8;          // smem row stride (bf16): +16B pad -> ldmatrix conflict-free
    constexpr int DIN = K / 2;
    constexpr int C8  = K / 8;          // uint4 (8 bf16) per row
    constexpr int NT  = DOUT / 16;      // n8-tiles per warp (covers DOUT/2)

    __shared__ __align__(16) __nv_bfloat16 As[64 * RS];
    __shared__ __align__(16) __nv_bfloat16 Wt[DOUT * RS];   // Wt[n][k] = Wcat[k][n]
    __shared__ float Bs[DOUT];

    int tid = threadIdx.x;
    int warp = tid >> 5, lane = tid & 31;
    int vbase = blockIdx.x * 64;

    // stage transposed concat weights (zero-pad k >= din_real in each half)
    for (int idx = tid; idx < DOUT * K; idx += 256) {
        int n = idx / K, k = idx % K;
        int kh = (k < DIN) ? k : k - DIN;
        float val = 0.0f;
        if (kh < din_real) val = ((k < DIN) ? Wsg : Wng)[kh * DOUT + n];
        Wt[n * RS + k] = __float2bfloat16(val);
    }
    if (tid < DOUT) Bs[tid] = Bg[tid];

    // stage activation tile [64][K] = [X | G]
    for (int idx = tid; idx < 64 * C8; idx += 256) {
        int r = idx / C8, c8 = idx % C8;
        int v = min(vbase + r, NV - 1);
        const __nv_bfloat16* src = (c8 < C8 / 2)
            ? &X[(size_t)v * DIN + c8 * 8]
            : &G[(size_t)v * DIN + (c8 - C8 / 2) * 8];
        *(uint4*)&As[r * RS + c8 * 8] = *(const uint4*)src;
    }
    __syncthreads();

    int wm = warp & 3;           // m-tile (16 rows)
    int wn = warp >> 2;          // n half
    int m0 = wm * 16;

    float d[NT][4];
#pragma unroll
    for (int nt = 0; nt < NT; nt++) {
        int n0 = wn * (DOUT / 2) + nt * 8;
        float c0 = Bs[n0 + (lane & 3) * 2];
        float c1 = Bs[n0 + (lane & 3) * 2 + 1];
        d[nt][0] = c0; d[nt][1] = c1; d[nt][2] = c0; d[nt][3] = c1;
    }

#pragma unroll
    for (int ks = 0; ks < K / 16; ks++) {
        int k0 = ks * 16;
        u32 a0, a1, a2, a3;
        u32 aaddr = smaddr(&As[(m0 + (lane & 15)) * RS + k0 + (lane >> 4) * 8]);
        ldsm_x4(a0, a1, a2, a3, aaddr);
#pragma unroll
        for (int nt = 0; nt < NT; nt++) {
            int n0 = wn * (DOUT / 2) + nt * 8;
            u32 b0, b1;
            u32 baddr = smaddr(&Wt[(n0 + (lane & 7)) * RS + k0 + ((lane >> 3) & 1) * 8]);
            ldsm_x2(b0, b1, baddr);
            mma_bf16(d[nt][0], d[nt][1], d[nt][2], d[nt][3], a0, a1, a2, a3, b0, b1);
        }
    }

    // epilogue: leaky relu + bf16 store
    int row0 = vbase + m0 + (lane >> 2);
#pragma unroll
    for (int nt = 0; nt < NT; nt++) {
        int col = wn * (DOUT / 2) + nt * 8 + (lane & 3) * 2;
        float y0 = d[nt][0], y1 = d[nt][1], y2 = d[nt][2], y3 = d[nt][3];
        if (RELU) {
            y0 = fmaxf(y0, 0.3f * y0); y1 = fmaxf(y1, 0.3f * y1);
            y2 = fmaxf(y2, 0.3f * y2); y3 = fmaxf(y3, 0.3f * y3);
        }
        if (row0 < NV)
            *(u32*)&Y[(size_t)row0 * DOUT + col] = f2bf2(pack2(y0, y1));
        if (row0 + 8 < NV)
            *(u32*)&Y[(size_t)(row0 + 8) * DOUT + col] = f2bf2(pack2(y2, y3));
    }
}

// ---------------- final layer, stage 1: project h3 by Ws3/Wn3 ----------------
__global__ void __launch_bounds__(256)
k_proj(const __nv_bfloat16* __restrict__ X,
       const float* __restrict__ Wsg, const float* __restrict__ Wng,
       const float* __restrict__ Bg)
{
    int t = threadIdx.x;
    int warp = t >> 5, lane = t & 31;

    float ws[2][3], wn[2][3];
#pragma unroll
    for (int e = 0; e < 2; e++)
#pragma unroll
        for (int c = 0; c < 3; c++) {
            ws[e][c] = Wsg[(2 * lane + e) * 3 + c];
            wn[e][c] = Wng[(2 * lane + e) * 3 + c];
        }

    int v = blockIdx.x * 8 + warp;
    if (v >= NV) return;

    u32 xp = *(const u32*)&X[(size_t)v * 64 + 2 * lane];
    float2 xv = unpack2(bf2f2(xp));

    float as[3], an[3];
#pragma unroll
    for (int c = 0; c < 3; c++) {
        as[c] = xv.x * ws[0][c] + xv.y * ws[1][c];
        an[c] = xv.x * wn[0][c] + xv.y * wn[1][c];
    }
#pragma unroll
    for (int off = 16; off > 0; off >>= 1) {
#pragma unroll
        for (int c = 0; c < 3; c++) {
            as[c] += __shfl_xor_sync(0xFFFFFFFFu, as[c], off);
            an[c] += __shfl_xor_sync(0xFFFFFFFFu, an[c], off);
        }
    }
    if (lane == 0) {
        g_S[v] = make_float4(as[0] + Bg[0], as[1] + Bg[1], as[2] + Bg[2], 0.0f);
        g_P[v] = make_float4(an[0], an[1], an[2], 0.0f);
    }
}

// ---------------- final layer, stage 2: 3-wide gather + output ----------------
__global__ void __launch_bounds__(256)
k_fin2(float* __restrict__ out, const float* __restrict__ verts)
{
    int v = blockIdx.x * blockDim.x + threadIdx.x;
    if (v >= NV) return;

    int d = g_cursor[v];
    int o = v * BCAP;
    float ax = 0.0f, ay = 0.0f, az = 0.0f;
    int k = 0;
    for (; k + 4 <= d; k += 4) {
        int s0 = g_csr[o + k],     s1 = g_csr[o + k + 1];
        int s2 = g_csr[o + k + 2], s3 = g_csr[o + k + 3];
        float4 p0 = g_P[s0], p1 = g_P[s1], p2 = g_P[s2], p3 = g_P[s3];
        ax += (p0.x + p1.x) + (p2.x + p3.x);
        ay += (p0.y + p1.y) + (p2.y + p3.y);
        az += (p0.z + p1.z) + (p2.z + p3.z);
    }
    for (; k < d; k++) {
        float4 p = g_P[g_csr[o + k]];
        ax += p.x; ay += p.y; az += p.z;
    }
    float idg = 1.0f / fmaxf((float)d, 1.0f);
    float4 S = g_S[v];
    out[v * 3 + 0] = verts[v * 3 + 0] + 0.1f * (S.x + idg * ax);
    out[v * 3 + 1] = verts[v * 3 + 1] + 0.1f * (S.y + idg * ay);
    out[v * 3 + 2] = verts[v * 3 + 2] + 0.1f * (S.z + idg * az);
}

// ---------------- launch ----------------
extern "C" void kernel_launch(void* const* d_in, const int* in_sizes, int n_in,
                              void* d_out, int out_size)
{
    const float* img   = (const float*)d_in[0];
    const float* verts = (const float*)d_in[1];
    const int*   esrc  = (const int*)d_in[2];
    const int*   edst  = (const int*)d_in[3];
    const float* ws0 = (const float*)d_in[4];
    const float* wn0 = (const float*)d_in[5];
    const float* b0  = (const float*)d_in[6];
    const float* ws1 = (const float*)d_in[7];
    const float* wn1 = (const float*)d_in[8];
    const float* b1  = (const float*)d_in[9];
    const float* ws2 = (const float*)d_in[10];
    const float* wn2 = (const float*)d_in[11];
    const float* b2  = (const float*)d_in[12];
    const float* ws3 = (const float*)d_in[13];
    const float* wn3 = (const float*)d_in[14];
    const float* b3  = (const float*)d_in[15];
    float* out = (float*)d_out;

    __nv_bfloat16 *x0p, *x1p, *x2p, *x3p, *g32p, *g64p;
    cudaGetSymbolAddress((void**)&x0p, g_X0);
    cudaGetSymbolAddress((void**)&x1p, g_X1);
    cudaGetSymbolAddress((void**)&x2p, g_X2);
    cudaGetSymbolAddress((void**)&x3p, g_X3);
    cudaGetSymbolAddress((void**)&g32p, g_G32);
    cudaGetSymbolAddress((void**)&g64p, g_G64);

    const int TB = 256;
    const int GB = (NV + 63) / 64;        // gemm blocks (64 verts each)
    const int GW = (NV + 7) / 8;          // warp-per-vertex grids

    k_sample<<<(NV * 16 + TB - 1) / TB, TB>>>(img, verts);
    k_scatter<<<(NE / 4 + TB - 1) / TB, TB>>>((const int4*)esrc, (const int4*)edst);

    k_gather32<<<(NV / 2 + 7) / 8, TB>>>(x0p, g32p);
    k_gemm<64, 32, true><<<GB, TB>>>(x0p, g32p, x1p, ws0, wn0, b0, 19);

    k_gather32<<<(NV / 2 + 7) / 8, TB>>>(x1p, g32p);
    k_gemm<64, 64, true><<<GB, TB>>>(x1p, g32p, x2p, ws1, wn1, b1, 32);

    k_gather64<<<GW, TB>>>(x2p, g64p);
    k_gemm<128, 64, true><<<GB, TB>>>(x2p, g64p, x3p, ws2, wn2, b2, 64);

    k_proj<<<GW, TB>>>(x3p, ws3, wn3, b3);
    k_fin2<<<(NV + TB - 1) / TB, TB>>>(out, verts);
}

// round 9
// speedup vs baseline: 2.1544x; 1.5785x over previous
#include <cuda_runtime.h>
#include <cuda_bf16.h>

typedef unsigned long long ull;
typedef unsigned int u32;

#define NV      100000
#define NE      1600000
#define GRIDW   128
#define G3      (GRIDW*GRIDW*GRIDW)
#define BCAP    128          // neighbor bucket capacity per vertex

// ---------------- device scratch ----------------
__device__ int   g_cursor[NV];
__device__ int   g_csr[NV * BCAP];

__device__ __align__(16) __nv_bfloat16 g_IT[G3 * 16];    // channels-last image (bf16)
__device__ __align__(16) __nv_bfloat16 g_X0[NV * 32];
__device__ __align__(16) __nv_bfloat16 g_X1[NV * 32];
__device__ __align__(16) __nv_bfloat16 g_X2[NV * 64];
__device__ __align__(16) __nv_bfloat16 g_X3[NV * 64];
__device__ __align__(16) __nv_bfloat16 g_G32[NV * 32];
__device__ __align__(16) __nv_bfloat16 g_G64[NV * 64];
__device__ float4 g_P[NV];    // h3 @ Wn3
__device__ float4 g_S[NV];    // h3 @ Ws3 + b3

// ---------------- helpers ----------------
__device__ __forceinline__ ull pack2(float lo, float hi) {
    ull r; asm("mov.b64 %0, {%1,%2};" : "=l"(r) : "f"(lo), "f"(hi)); return r;
}
__device__ __forceinline__ float2 unpack2(ull v) {
    float2 f; asm("mov.b64 {%0,%1}, %2;" : "=f"(f.x), "=f"(f.y) : "l"(v)); return f;
}
__device__ __forceinline__ ull add2(ull a, ull b) {
    ull d; asm("add.rn.f32x2 %0, %1, %2;" : "=l"(d) : "l"(a), "l"(b)); return d;
}
__device__ __forceinline__ ull mul2(ull a, ull b) {
    ull d; asm("mul.rn.f32x2 %0, %1, %2;" : "=l"(d) : "l"(a), "l"(b)); return d;
}
__device__ __forceinline__ ull bf2f2(u32 p) {
    u32 lo = p << 16;
    u32 hi = p & 0xFFFF0000u;
    ull r; asm("mov.b64 %0, {%1,%2};" : "=l"(r) : "r"(lo), "r"(hi)); return r;
}
__device__ __forceinline__ u32 f2bf2(ull v) {
    float2 f = unpack2(v);
    __nv_bfloat162 b = __float22bfloat162_rn(f);
    return *(u32*)&b;
}
__device__ __forceinline__ u32 f2bf2s(float lo, float hi) {
    __nv_bfloat162 b = __float22bfloat162_rn(make_float2(lo, hi));
    return *(u32*)&b;
}
__device__ __forceinline__ u32 smaddr(const void* p) {
    return (u32)__cvta_generic_to_shared(p);
}
__device__ __forceinline__ void ldsm_x4(u32& r0, u32& r1, u32& r2, u32& r3, u32 a) {
    asm volatile("ldmatrix.sync.aligned.m8n8.x4.shared.b16 {%0,%1,%2,%3}, [%4];"
                 : "=r"(r0), "=r"(r1), "=r"(r2), "=r"(r3) : "r"(a));
}
__device__ __forceinline__ void ldsm_x2(u32& r0, u32& r1, u32 a) {
    asm volatile("ldmatrix.sync.aligned.m8n8.x2.shared.b16 {%0,%1}, [%2];"
                 : "=r"(r0), "=r"(r1) : "r"(a));
}
__device__ __forceinline__ void mma_bf16(float& d0, float& d1, float& d2, float& d3,
                                         u32 a0, u32 a1, u32 a2, u32 a3,
                                         u32 b0, u32 b1) {
    asm volatile(
        "mma.sync.aligned.m16n8k16.row.col.f32.bf16.bf16.f32 "
        "{%0,%1,%2,%3}, {%4,%5,%6,%7}, {%8,%9}, {%0,%1,%2,%3};"
        : "+f"(d0), "+f"(d1), "+f"(d2), "+f"(d3)
        : "r"(a0), "r"(a1), "r"(a2), "r"(a3), "r"(b0), "r"(b1));
}

// ---------------- image transpose: [16][x][y][z] f32 -> [x][y][z][16] bf16 ----------------
__global__ void __launch_bounds__(128)
k_transpose(const float* __restrict__ img)
{
    __shared__ __align__(16) __nv_bfloat16 s[128 * 16];   // [z][c]
    int xy = blockIdx.x;              // x*128 + y
    int z = threadIdx.x;
    int base = xy * 128;              // voxel index of (x,y,0)
#pragma unroll
    for (int c = 0; c < 16; c++) {
        float v = img[(size_t)c * G3 + base + z];
        s[z * 16 + c] = __float2bfloat16(v);
    }
    __syncthreads();
    // write 128*16 bf16 = 256 uint4, contiguous
    const uint4* sp = (const uint4*)s;
    uint4* gp = (uint4*)&g_IT[(size_t)base * 16];
    gp[z]       = sp[z];
    gp[z + 128] = sp[z + 128];
}

// ---------------- bucket scatter ----------------
__global__ void k_scatter(const int4* __restrict__ src4, const int4* __restrict__ dst4) {
    int e = blockIdx.x * blockDim.x + threadIdx.x;
    if (e < NE / 4) {
        int4 s = src4[e];
        int4 d = dst4[e];
        int p;
        p = atomicAdd(&g_cursor[d.x], 1); g_csr[d.x * BCAP + p] = s.x;
        p = atomicAdd(&g_cursor[d.y], 1); g_csr[d.y * BCAP + p] = s.y;
        p = atomicAdd(&g_cursor[d.z], 1); g_csr[d.z * BCAP + p] = s.z;
        p = atomicAdd(&g_cursor[d.w], 1); g_csr[d.w * BCAP + p] = s.w;
    }
}

// ---------------- trilinear sampling from channels-last bf16 volume ----------------
// One thread per vertex: 8 corners x 2 LDG.128; all 16 channels at once.
__global__ void __launch_bounds__(256)
k_sample(const float* __restrict__ verts)
{
    int v = blockIdx.x * blockDim.x + threadIdx.x;
    if (v >= NV) return;

    g_cursor[v] = 0;

    float px = verts[v * 3 + 0];
    float py = verts[v * 3 + 1];
    float pz = verts[v * 3 + 2];

    float cx = fminf(fmaxf(px, 0.0f), 127.0f);
    float cy = fminf(fmaxf(py, 0.0f), 127.0f);
    float cz = fminf(fmaxf(pz, 0.0f), 127.0f);
    float fx0 = floorf(cx), fy0 = floorf(cy), fz0 = floorf(cz);
    int x0 = (int)fx0, y0 = (int)fy0, z0 = (int)fz0;
    int x1 = min(x0 + 1, 127), y1 = min(y0 + 1, 127), z1 = min(z0 + 1, 127);
    float wx = cx - fx0, wy = cy - fy0, wz = cz - fz0;

    float f[16];
#pragma unroll
    for (int c = 0; c < 16; c++) f[c] = 0.0f;

    int xs[2] = {x0, x1}; int ys[2] = {y0, y1}; int zs[2] = {z0, z1};
    float wxa[2] = {1.0f - wx, wx};
    float wya[2] = {1.0f - wy, wy};
    float wza[2] = {1.0f - wz, wz};

#pragma unroll
    for (int a = 0; a < 2; a++)
#pragma unroll
    for (int b = 0; b < 2; b++)
#pragma unroll
    for (int cc = 0; cc < 2; cc++) {
        float w = wxa[a] * wya[b] * wza[cc];
        size_t idx = ((size_t)((xs[a] << 14) + (ys[b] << 7) + zs[cc])) << 4;
        uint4 p0 = *(const uint4*)&g_IT[idx];
        uint4 p1 = *(const uint4*)&g_IT[idx + 8];
        const u32 pk[8] = {p0.x, p0.y, p0.z, p0.w, p1.x, p1.y, p1.z, p1.w};
#pragma unroll
        for (int j = 0; j < 8; j++) {
            float2 two = unpack2(bf2f2(pk[j]));
            f[2 * j]     += w * two.x;
            f[2 * j + 1] += w * two.y;
        }
    }

    // pack row: [cx,cy,cz]/128, f0..f15, zeros -> 32 bf16 = 4 uint4
    float e[32];
    e[0] = px * (1.0f / 128.0f);
    e[1] = py * (1.0f / 128.0f);
    e[2] = pz * (1.0f / 128.0f);
#pragma unroll
    for (int c = 0; c < 16; c++) e[3 + c] = f[c];
#pragma unroll
    for (int c = 19; c < 32; c++) e[c] = 0.0f;

    u32 w8[16];
#pragma unroll
    for (int j = 0; j < 16; j++) w8[j] = f2bf2s(e[2 * j], e[2 * j + 1]);
    uint4* dst = (uint4*)&g_X0[(size_t)v * 32];
    dst[0] = make_uint4(w8[0], w8[1], w8[2], w8[3]);
    dst[1] = make_uint4(w8[4], w8[5], w8[6], w8[7]);
    dst[2] = make_uint4(w8[8], w8[9], w8[10], w8[11]);
    dst[3] = make_uint4(w8[12], w8[13], w8[14], w8[15]);
}

// ---------------- gather: mean of neighbor rows (64-wide), warp/vertex ----------------
__global__ void __launch_bounds__(256)
k_gather64(const __nv_bfloat16* __restrict__ X, __nv_bfloat16* __restrict__ G)
{
    int warp = threadIdx.x >> 5, lane = threadIdx.x & 31;
    int v = blockIdx.x * 8 + warp;
    if (v >= NV) return;

    int d = g_cursor[v];
    int o = v * BCAP;
    ull acc = 0ull;
    for (int kb = 0; kb < d; kb += 32) {
        int idx = (kb + lane < d) ? g_csr[o + kb + lane] : 0;
        int klim = min(d - kb, 32);
#pragma unroll 4
        for (int k = 0; k < klim; k++) {
            int s = __shfl_sync(0xFFFFFFFFu, idx, k);
            u32 p = *(const u32*)&X[(size_t)s * 64 + 2 * lane];
            acc = add2(acc, bf2f2(p));
        }
    }
    float inv = 1.0f / fmaxf((float)d, 1.0f);
    acc = mul2(acc, pack2(inv, inv));
    *(u32*)&G[(size_t)v * 64 + 2 * lane] = f2bf2(acc);
}

// ---------------- gather (32-wide): warp handles 2 vertices ----------------
__global__ void __launch_bounds__(256)
k_gather32(const __nv_bfloat16* __restrict__ X, __nv_bfloat16* __restrict__ G)
{
    int warp = threadIdx.x >> 5, lane = threadIdx.x & 31;
    int hl = lane & 15, half = lane >> 4;
    int v0 = (blockIdx.x * 8 + warp) * 2;
    if (v0 >= NV) return;

    int vme = v0 + half;
    int dA = g_cursor[v0], dB = g_cursor[v0 + 1];
    int dme = half ? dB : dA;
    int o = vme * BCAP;
    int dmax = max(dA, dB);

    ull acc = 0ull;
    for (int kb = 0; kb < dmax; kb += 16) {
        int idx = (kb + hl < dme) ? g_csr[o + kb + hl] : 0;
        int klim = min(dmax - kb, 16);
#pragma unroll 4
        for (int k = 0; k < klim; k++) {
            int s = __shfl_sync(0xFFFFFFFFu, idx, (half << 4) + k);
            if (kb + k < dme) {
                u32 p = *(const u32*)&X[(size_t)s * 32 + 2 * hl];
                acc = add2(acc, bf2f2(p));
            }
        }
    }
    float inv = 1.0f / fmaxf((float)dme, 1.0f);
    acc = mul2(acc, pack2(inv, inv));
    *(u32*)&G[(size_t)vme * 32 + 2 * hl] = f2bf2(acc);
}

// ---------------- tensor-core layer GEMM ----------------
// Y[M x DOUT] = leaky([X|G][M x K] @ Wt^T + b). M in {64,128}.
// 8 warps: 4 m-tile groups x 2 n-halves; each warp does M/64 m-subtiles.
template<int M, int K, int DOUT, bool RELU>
__global__ void __launch_bounds__(256)
k_gemm(const __nv_bfloat16* __restrict__ X, const __nv_bfloat16* __restrict__ G,
       __nv_bfloat16* __restrict__ Y,
       const float* __restrict__ Wsg, const float* __restrict__ Wng,
       const float* __restrict__ Bg, int din_real)
{
    constexpr int RS  = K + 8;
    constexpr int DIN = K / 2;
    constexpr int C8  = K / 8;
    constexpr int NT  = DOUT / 16;      // n8-tiles per warp
    constexpr int MH  = M / 64;         // m-subtiles per warp (1 or 2)

    __shared__ __align__(16) __nv_bfloat16 As[M * RS];
    __shared__ __align__(16) __nv_bfloat16 Wt[DOUT * RS];
    __shared__ float Bs[DOUT];

    int tid = threadIdx.x;
    int warp = tid >> 5, lane = tid & 31;
    int vbase = blockIdx.x * M;

    for (int idx = tid; idx < DOUT * K; idx += 256) {
        int n = idx / K, k = idx % K;
        int kh = (k < DIN) ? k : k - DIN;
        float val = 0.0f;
        if (kh < din_real) val = ((k < DIN) ? Wsg : Wng)[kh * DOUT + n];
        Wt[n * RS + k] = __float2bfloat16(val);
    }
    if (tid < DOUT) Bs[tid] = Bg[tid];

    for (int idx = tid; idx < M * C8; idx += 256) {
        int r = idx / C8, c8 = idx % C8;
        int v = min(vbase + r, NV - 1);
        const __nv_bfloat16* src = (c8 < C8 / 2)
            ? &X[(size_t)v * DIN + c8 * 8]
            : &G[(size_t)v * DIN + (c8 - C8 / 2) * 8];
        *(uint4*)&As[r * RS + c8 * 8] = *(const uint4*)src;
    }
    __syncthreads();

    int wm = warp & 3;
    int wn = warp >> 2;
    int nb = wn * (DOUT / 2);

    float d[MH][NT][4];
#pragma unroll
    for (int nt = 0; nt < NT; nt++) {
        float c0 = Bs[nb + nt * 8 + (lane & 3) * 2];
        float c1 = Bs[nb + nt * 8 + (lane & 3) * 2 + 1];
#pragma unroll
        for (int mh = 0; mh < MH; mh++) {
            d[mh][nt][0] = c0; d[mh][nt][1] = c1;
            d[mh][nt][2] = c0; d[mh][nt][3] = c1;
        }
    }

#pragma unroll
    for (int ks = 0; ks < K / 16; ks++) {
        int k0 = ks * 16;
        u32 a[MH][4];
#pragma unroll
        for (int mh = 0; mh < MH; mh++) {
            int m0 = mh * 64 + wm * 16;
            u32 aaddr = smaddr(&As[(m0 + (lane & 15)) * RS + k0 + (lane >> 4) * 8]);
            ldsm_x4(a[mh][0], a[mh][1], a[mh][2], a[mh][3], aaddr);
        }
#pragma unroll
        for (int nt = 0; nt < NT; nt++) {
            u32 b0, b1;
            u32 baddr = smaddr(&Wt[(nb + nt * 8 + (lane & 7)) * RS + k0 + ((lane >> 3) & 1) * 8]);
            ldsm_x2(b0, b1, baddr);
#pragma unroll
            for (int mh = 0; mh < MH; mh++)
                mma_bf16(d[mh][nt][0], d[mh][nt][1], d[mh][nt][2], d[mh][nt][3],
                         a[mh][0], a[mh][1], a[mh][2], a[mh][3], b0, b1);
        }
    }

#pragma unroll
    for (int mh = 0; mh < MH; mh++) {
        int row0 = vbase + mh * 64 + wm * 16 + (lane >> 2);
#pragma unroll
        for (int nt = 0; nt < NT; nt++) {
            int col = nb + nt * 8 + (lane & 3) * 2;
            float y0 = d[mh][nt][0], y1 = d[mh][nt][1], y2 = d[mh][nt][2], y3 = d[mh][nt][3];
            if (RELU) {
                y0 = fmaxf(y0, 0.3f * y0); y1 = fmaxf(y1, 0.3f * y1);
                y2 = fmaxf(y2, 0.3f * y2); y3 = fmaxf(y3, 0.3f * y3);
            }
            if (row0 < NV)
                *(u32*)&Y[(size_t)row0 * DOUT + col] = f2bf2s(y0, y1);
            if (row0 + 8 < NV)
                *(u32*)&Y[(size_t)(row0 + 8) * DOUT + col] = f2bf2s(y2, y3);
        }
    }
}

// ---------------- final layer, stage 1: project h3 by Ws3/Wn3 ----------------
__global__ void __launch_bounds__(256)
k_proj(const __nv_bfloat16* __restrict__ X,
       const float* __restrict__ Wsg, const float* __restrict__ Wng,
       const float* __restrict__ Bg)
{
    int t = threadIdx.x;
    int warp = t >> 5, lane = t & 31;

    float ws[2][3], wn[2][3];
#pragma unroll
    for (int e = 0; e < 2; e++)
#pragma unroll
        for (int c = 0; c < 3; c++) {
            ws[e][c] = Wsg[(2 * lane + e) * 3 + c];
            wn[e][c] = Wng[(2 * lane + e) * 3 + c];
        }

    int v = blockIdx.x * 8 + warp;
    if (v >= NV) return;

    u32 xp = *(const u32*)&X[(size_t)v * 64 + 2 * lane];
    float2 xv = unpack2(bf2f2(xp));

    float as[3], an[3];
#pragma unroll
    for (int c = 0; c < 3; c++) {
        as[c] = xv.x * ws[0][c] + xv.y * ws[1][c];
        an[c] = xv.x * wn[0][c] + xv.y * wn[1][c];
    }
#pragma unroll
    for (int off = 16; off > 0; off >>= 1) {
#pragma unroll
        for (int c = 0; c < 3; c++) {
            as[c] += __shfl_xor_sync(0xFFFFFFFFu, as[c], off);
            an[c] += __shfl_xor_sync(0xFFFFFFFFu, an[c], off);
        }
    }
    if (lane == 0) {
        g_S[v] = make_float4(as[0] + Bg[0], as[1] + Bg[1], as[2] + Bg[2], 0.0f);
        g_P[v] = make_float4(an[0], an[1], an[2], 0.0f);
    }
}

// ---------------- final layer, stage 2: 3-wide gather + output ----------------
__global__ void __launch_bounds__(256)
k_fin2(float* __restrict__ out, const float* __restrict__ verts)
{
    int v = blockIdx.x * blockDim.x + threadIdx.x;
    if (v >= NV) return;

    int d = g_cursor[v];
    int o = v * BCAP;
    float ax = 0.0f, ay = 0.0f, az = 0.0f;
    int k = 0;
    for (; k + 4 <= d; k += 4) {
        int s0 = g_csr[o + k],     s1 = g_csr[o + k + 1];
        int s2 = g_csr[o + k + 2], s3 = g_csr[o + k + 3];
        float4 p0 = g_P[s0], p1 = g_P[s1], p2 = g_P[s2], p3 = g_P[s3];
        ax += (p0.x + p1.x) + (p2.x + p3.x);
        ay += (p0.y + p1.y) + (p2.y + p3.y);
        az += (p0.z + p1.z) + (p2.z + p3.z);
    }
    for (; k < d; k++) {
        float4 p = g_P[g_csr[o + k]];
        ax += p.x; ay += p.y; az += p.z;
    }
    float idg = 1.0f / fmaxf((float)d, 1.0f);
    float4 S = g_S[v];
    out[v * 3 + 0] = verts[v * 3 + 0] + 0.1f * (S.x + idg * ax);
    out[v * 3 + 1] = verts[v * 3 + 1] + 0.1f * (S.y + idg * ay);
    out[v * 3 + 2] = verts[v * 3 + 2] + 0.1f * (S.z + idg * az);
}

// ---------------- launch ----------------
extern "C" void kernel_launch(void* const* d_in, const int* in_sizes, int n_in,
                              void* d_out, int out_size)
{
    const float* img   = (const float*)d_in[0];
    const float* verts = (const float*)d_in[1];
    const int*   esrc  = (const int*)d_in[2];
    const int*   edst  = (const int*)d_in[3];
    const float* ws0 = (const float*)d_in[4];
    const float* wn0 = (const float*)d_in[5];
    const float* b0  = (const float*)d_in[6];
    const float* ws1 = (const float*)d_in[7];
    const float* wn1 = (const float*)d_in[8];
    const float* b1  = (const float*)d_in[9];
    const float* ws2 = (const float*)d_in[10];
    const float* wn2 = (const float*)d_in[11];
    const float* b2  = (const float*)d_in[12];
    const float* ws3 = (const float*)d_in[13];
    const float* wn3 = (const float*)d_in[14];
    const float* b3  = (const float*)d_in[15];
    float* out = (float*)d_out;

    __nv_bfloat16 *x0p, *x1p, *x2p, *x3p, *g32p, *g64p;
    cudaGetSymbolAddress((void**)&x0p, g_X0);
    cudaGetSymbolAddress((void**)&x1p, g_X1);
    cudaGetSymbolAddress((void**)&x2p, g_X2);
    cudaGetSymbolAddress((void**)&x3p, g_X3);
    cudaGetSymbolAddress((void**)&g32p, g_G32);
    cudaGetSymbolAddress((void**)&g64p, g_G64);

    const int TB = 256;
    const int GW = (NV + 7) / 8;

    k_transpose<<<GRIDW * GRIDW, 128>>>(img);
    k_scatter<<<(NE / 4 + TB - 1) / TB, TB>>>((const int4*)esrc, (const int4*)edst);
    k_sample<<<(NV + TB - 1) / TB, TB>>>(verts);

    k_gather32<<<(NV / 2 + 7) / 8, TB>>>(x0p, g32p);
    k_gemm<128, 64, 32, true><<<(NV + 127) / 128, TB>>>(x0p, g32p, x1p, ws0, wn0, b0, 19);

    k_gather32<<<(NV / 2 + 7) / 8, TB>>>(x1p, g32p);
    k_gemm<128, 64, 64, true><<<(NV + 127) / 128, TB>>>(x1p, g32p, x2p, ws1, wn1, b1, 32);

    k_gather64<<<GW, TB>>>(x2p, g64p);
    k_gemm<64, 128, 64, true><<<(NV + 63) / 64, TB>>>(x2p, g64p, x3p, ws2, wn2, b2, 64);

    k_proj<<<GW, TB>>>(x3p, ws3, wn3, b3);
    k_fin2<<<(NV + TB - 1) / TB, TB>>>(out, verts);
}